// round 16
// baseline (speedup 1.0000x reference)
#include <cuda_runtime.h>
#include <cuda_fp16.h>
#include <string.h>

// GooLayer: B=2, M=64, D=64, T=8192 — chunked linear-scan, batch-split for
// L2-resident g scratch + sub-chunk parallelism in pass B:
//   K0: homogeneous M^256 and M^512 per (m,d)
//   per batch b in {0,1}:  K1(b) -> K2(b) -> K3(b)
// K1 writes g'=(f+ki*h)*(gain*DAMP) fp16 (noise-shaped) into a 67MB buffer
// reused by both batches (K3 reads it from L2; K1(b=1) overwrites the dirty
// lines). K1 also emits mid-chunk (256-step) states so K2 can hand K3
// 32 sub-chunk ICs -> 2048 warp-units per batch in K3.

#define MMX 64
#define DDX 64
#define TTX 8192
#define DAMP 0.9998f
#define NCH 16
#define NSC 32                          // 256-step sub-chunks
#define CL (TTX / NCH)                  // 512
#define NW8 (CL / 8)                    // 64 fp16-octet windows per chunk
#define K1NT (CL / 32)                  // 16 staging tiles per chunk
#define FQ (TTX / 4)                    // float4 per chain (2048)

// g scratch for ONE batch: [bmL][chunk][w8][d] -> uint4 (8 fp16). 67MB.
__device__ uint4 g_scr[(size_t)MMX * NCH * NW8 * DDX];
__device__ float g_fin[MMX * NCH * DDX * 2];
__device__ float g_mid[MMX * NCH * DDX * 2];
__device__ float g_ic [MMX * NSC * DDX * 2];
__device__ float4 g_hom256[MMX * DDX];  // M^256 columns {p1,v1,p2,v2}
__device__ float4 g_hom512[MMX * DDX];  // M^512 columns

__device__ __forceinline__ float tanh_fast(float x) {
    float y; asm("tanh.approx.f32 %0, %1;" : "=f"(y) : "f"(x)); return y;
}
__device__ __forceinline__ __half2 u32_as_half2(unsigned u) {
    __half2 h; memcpy(&h, &u, 4); return h;
}
__device__ __forceinline__ unsigned half2_as_u32(__half2 h) {
    unsigned u; memcpy(&u, &h, 4); return u;
}

// ---------------- K0: homogeneous M^256 / M^512 per (m,d) ----------------
__global__ __launch_bounds__(256)
void k0_homog(const float* __restrict__ masses, const float* __restrict__ tensions)
{
    int idx = blockIdx.x * 256 + threadIdx.x;      // m*64+d, 0..4095
    int m = idx >> 6;
    float nki = -(tensions[idx] / masses[m]);
    float p1 = 1.f, v1 = 0.f, p2 = 0.f, v2 = 1.f;
    #pragma unroll 8
    for (int t = 0; t < CL / 2; t++) {
        v1 = fmaf(v1, DAMP, nki * p1); p1 = fmaf(v1, DAMP, p1);
        v2 = fmaf(v2, DAMP, nki * p2); p2 = fmaf(v2, DAMP, p2);
    }
    g_hom256[idx] = make_float4(p1, v1, p2, v2);
    #pragma unroll 8
    for (int t = 0; t < CL / 2; t++) {
        v1 = fmaf(v1, DAMP, nki * p1); p1 = fmaf(v1, DAMP, p1);
        v2 = fmaf(v2, DAMP, nki * p2); p2 = fmaf(v2, DAMP, p2);
    }
    g_hom512[idx] = make_float4(p1, v1, p2, v2);
}

// ---------------- K1: pass A (one batch) ----------------
// 128 threads = 4 warps; one warp per (bmL, chunk, half). 512 blocks/batch.
__global__ __launch_bounds__(128)
void k1_passA(const float* __restrict__ forces, const float* __restrict__ home,
              const float* __restrict__ masses, const float* __restrict__ tensions,
              const float* __restrict__ gains, int batch)
{
    __shared__ float gt[4][32][36];   // staged g' tiles: [warp][chain][t]
    __shared__ float kis[4][32];

    const int tid = threadIdx.x, wid = tid >> 5, lane = tid & 31;
    const int unit  = blockIdx.x * 4 + wid;        // 0..2047
    const int bmL   = unit >> 5;                   // 0..63 (= m)
    const int chunk = (unit >> 1) & 15;
    const int half  = unit & 1;
    const int m = bmL;
    const int d = half * 32 + lane;
    const int bmG = batch * 64 + bmL;

    const float ki   = tensions[m * 64 + d] / masses[m];
    const float nki  = -ki;
    const float karg = gains[m] * DAMP;            // state scale (tanh arg)

    kis[wid][lane] = ki;
    __syncwarp();

    // per LDG.128: lanes cover 4 chains x 8 float4 (full 128B lines)
    const int lch4 = lane >> 3;                    // 0..3
    const int lt8  = lane & 7;                     // 0..7
    const size_t wb = ((size_t)(bmG * 64 + half * 32)) * TTX + (size_t)chunk * CL;
    const float4* __restrict__ fbase = (const float4*)(forces + wb) + lt8;
    const float4* __restrict__ hbase = (const float4*)(home  + wb) + lt8;

    float kk0 = kis[wid][ 0 + lch4], kk1 = kis[wid][ 4 + lch4];
    float kk2 = kis[wid][ 8 + lch4], kk3 = kis[wid][12 + lch4];
    float kk4 = kis[wid][16 + lch4], kk5 = kis[wid][20 + lch4];
    float kk6 = kis[wid][24 + lch4], kk7 = kis[wid][28 + lch4];

    uint4* gw = g_scr + ((size_t)(bmL * NCH + chunk) * NW8) * 64 + d;

    float pos = 0.f, vs = 0.f, e = 0.f;            // karg-scaled state

    float4 nf0, nf1, nf2, nf3, nf4, nf5, nf6, nf7;
    float4 nh0, nh1, nh2, nh3, nh4, nh5, nh6, nh7;

#define K1_LDALL(OFF)                                                          \
    nf0 = __ldcs(fbase + (size_t)(0 * 4 + lch4) * FQ + (OFF));                 \
    nf1 = __ldcs(fbase + (size_t)(1 * 4 + lch4) * FQ + (OFF));                 \
    nf2 = __ldcs(fbase + (size_t)(2 * 4 + lch4) * FQ + (OFF));                 \
    nf3 = __ldcs(fbase + (size_t)(3 * 4 + lch4) * FQ + (OFF));                 \
    nf4 = __ldcs(fbase + (size_t)(4 * 4 + lch4) * FQ + (OFF));                 \
    nf5 = __ldcs(fbase + (size_t)(5 * 4 + lch4) * FQ + (OFF));                 \
    nf6 = __ldcs(fbase + (size_t)(6 * 4 + lch4) * FQ + (OFF));                 \
    nf7 = __ldcs(fbase + (size_t)(7 * 4 + lch4) * FQ + (OFF));                 \
    nh0 = __ldcs(hbase + (size_t)(0 * 4 + lch4) * FQ + (OFF));                 \
    nh1 = __ldcs(hbase + (size_t)(1 * 4 + lch4) * FQ + (OFF));                 \
    nh2 = __ldcs(hbase + (size_t)(2 * 4 + lch4) * FQ + (OFF));                 \
    nh3 = __ldcs(hbase + (size_t)(3 * 4 + lch4) * FQ + (OFF));                 \
    nh4 = __ldcs(hbase + (size_t)(4 * 4 + lch4) * FQ + (OFF));                 \
    nh5 = __ldcs(hbase + (size_t)(5 * 4 + lch4) * FQ + (OFF));                 \
    nh6 = __ldcs(hbase + (size_t)(6 * 4 + lch4) * FQ + (OFF));                 \
    nh7 = __ldcs(hbase + (size_t)(7 * 4 + lch4) * FQ + (OFF));

#define K1_G4(NF, NH, KK)                                                      \
    make_float4(fmaf(KK, NH.x, NF.x) * karg, fmaf(KK, NH.y, NF.y) * karg,      \
                fmaf(KK, NH.z, NF.z) * karg, fmaf(KK, NH.w, NF.w) * karg)

    K1_LDALL(0)

    for (int tile = 0; tile < K1NT; tile++) {
        float4 ng0 = K1_G4(nf0, nh0, kk0), ng1 = K1_G4(nf1, nh1, kk1);
        float4 ng2 = K1_G4(nf2, nh2, kk2), ng3 = K1_G4(nf3, nh3, kk3);
        float4 ng4 = K1_G4(nf4, nh4, kk4), ng5 = K1_G4(nf5, nh5, kk5);
        float4 ng6 = K1_G4(nf6, nh6, kk6), ng7 = K1_G4(nf7, nh7, kk7);

        __syncwarp();
        *(float4*)&gt[wid][ 0 + lch4][lt8 * 4] = ng0;
        *(float4*)&gt[wid][ 4 + lch4][lt8 * 4] = ng1;
        *(float4*)&gt[wid][ 8 + lch4][lt8 * 4] = ng2;
        *(float4*)&gt[wid][12 + lch4][lt8 * 4] = ng3;
        *(float4*)&gt[wid][16 + lch4][lt8 * 4] = ng4;
        *(float4*)&gt[wid][20 + lch4][lt8 * 4] = ng5;
        *(float4*)&gt[wid][24 + lch4][lt8 * 4] = ng6;
        *(float4*)&gt[wid][28 + lch4][lt8 * 4] = ng7;
        __syncwarp();

        if (tile + 1 < K1NT) { K1_LDALL((tile + 1) * 8) }

        // 32 steps for chain = lane; quantize with 1-way error feedback
        unsigned uq0 = 0, uq1 = 0;
        #pragma unroll
        for (int j = 0; j < 8; j++) {
            float4 gv = *(const float4*)&gt[wid][lane][4 * j];
            __half q0, q1, q2, q3;
            float t, r, acc;

            t = gv.x + e; q0 = __float2half_rn(t); r = __half2float(q0); e = t - r;
            acc = fmaf(nki, pos, r); vs = fmaf(vs, DAMP, acc); pos = fmaf(vs, DAMP, pos);
            t = gv.y + e; q1 = __float2half_rn(t); r = __half2float(q1); e = t - r;
            acc = fmaf(nki, pos, r); vs = fmaf(vs, DAMP, acc); pos = fmaf(vs, DAMP, pos);
            t = gv.z + e; q2 = __float2half_rn(t); r = __half2float(q2); e = t - r;
            acc = fmaf(nki, pos, r); vs = fmaf(vs, DAMP, acc); pos = fmaf(vs, DAMP, pos);
            t = gv.w + e; q3 = __float2half_rn(t); r = __half2float(q3); e = t - r;
            acc = fmaf(nki, pos, r); vs = fmaf(vs, DAMP, acc); pos = fmaf(vs, DAMP, pos);

            unsigned ua = half2_as_u32(__halves2half2(q0, q1));  // q0 low
            unsigned ub = half2_as_u32(__halves2half2(q2, q3));
            if ((j & 1) == 0) { uq0 = ua; uq1 = ub; }
            else {
                uint4 pk; pk.x = uq0; pk.y = uq1; pk.z = ua; pk.w = ub;
                // evict-normal store: keep g resident in L2 for K3
                gw[(size_t)(tile * 4 + (j >> 1)) * 64] = pk;
            }
        }

        if (tile == K1NT / 2 - 1) {   // state after 256 steps
            float* mid = g_mid + ((size_t)(bmL * NCH + chunk) * 64 + d) * 2;
            mid[0] = pos; mid[1] = vs;
        }
    }
#undef K1_LDALL
#undef K1_G4

    float* fin = g_fin + ((size_t)(bmL * NCH + chunk) * 64 + d) * 2;
    fin[0] = pos; fin[1] = vs;
}

// ---------------- K2: combine (one batch): 32 sub-chunk ICs ----------------
__global__ __launch_bounds__(256)
void k2_combine()
{
    int idx = blockIdx.x * 256 + threadIdx.x;      // bmL*64+d, 0..4095
    int bmL = idx >> 6, d = idx & 63;
    float4 H = g_hom256[idx];                       // M^256 {p1,v1,p2,v2}
    float4 A = g_hom512[idx];                       // M^512
    float pos = 0.f, vs = 0.f;
    #pragma unroll
    for (int c = 0; c < NCH; c++) {
        size_t om = ((size_t)(bmL * NCH + c) * 64 + d) * 2;
        size_t oi = ((size_t)(bmL * NSC + 2 * c) * 64 + d) * 2;
        g_ic[oi] = pos; g_ic[oi + 1] = vs;
        float mp = fmaf(H.x, pos, fmaf(H.z, vs, g_mid[om]));
        float mv = fmaf(H.y, pos, fmaf(H.w, vs, g_mid[om + 1]));
        size_t oj = ((size_t)(bmL * NSC + 2 * c + 1) * 64 + d) * 2;
        g_ic[oj] = mp; g_ic[oj + 1] = mv;
        float np = fmaf(A.x, pos, fmaf(A.z, vs, g_fin[om]));
        float nv = fmaf(A.y, pos, fmaf(A.w, vs, g_fin[om + 1]));
        pos = np; vs = nv;
    }
}

// ---------------- K3: pass B (one batch) — warp per (bmL, sub-chunk) ------
__global__ __launch_bounds__(128)
void k3_passB(const float* __restrict__ mic, const float* __restrict__ masses,
              const float* __restrict__ tensions, float* __restrict__ out,
              int batch)
{
    __shared__ float tile_s[4][16][36];

    const int tid = threadIdx.x, wid = tid >> 5, lane = tid & 31;
    const int unit = blockIdx.x * 4 + wid;         // 0..2047
    const int bmL  = unit >> 5;
    const int sc   = unit & 31;                    // sub-chunk (256 steps)
    const int chunk = sc >> 1;
    const int m = bmL;
    const int bmG = batch * 64 + bmL;
    const int d0 = lane, d1 = lane + 32;

    const float inv_mass = 1.f / masses[m];
    const float nki0 = -(tensions[m * 64 + d0] * inv_mass);
    const float nki1 = -(tensions[m * 64 + d1] * inv_mass);
    const float micv0 = mic[bmG * 64 + d0];
    const float micv1 = mic[bmG * 64 + d1];

    const uint4* gw0 = g_scr + ((size_t)((bmL * NCH + chunk) * NW8)
                                + (size_t)(sc & 1) * (NW8 / 2)) * 64 + d0;
    const uint4* gw1 = gw0 + 32;
    const size_t ib = ((size_t)(bmL * NSC + sc) * 64) * 2;
    float pos0 = g_ic[ib + 2 * d0], vs0 = g_ic[ib + 2 * d0 + 1];
    float pos1 = g_ic[ib + 2 * d1], vs1 = g_ic[ib + 2 * d1 + 1];
    float* obase = out + (size_t)bmG * TTX + (size_t)sc * (CL / 2);
    float (*tile)[36] = tile_s[wid];

    uint4 ca00, ca01, ca10, ca11, cb00, cb01, cb10, cb11;
    ca00 = gw0[0];  ca01 = gw0[64];   // default policy: L2 hits from K1
    ca10 = gw1[0];  ca11 = gw1[64];

    const int NWND = (CL / 2) / 16;                // 16 windows of 16 steps

#define K3_QQ(G0, G1, R)                                                       \
    _Pragma("unroll")                                                          \
    for (int i = 0; i < 4; i++) {                                              \
        float2 fa = __half22float2(u32_as_half2((&G0.x)[i]));                  \
        float2 fb = __half22float2(u32_as_half2((&G1.x)[i]));                  \
        _Pragma("unroll")                                                      \
        for (int s = 0; s < 2; s++) {                                          \
            float gv0 = s ? fa.y : fa.x;                                       \
            float gv1 = s ? fb.y : fb.x;                                       \
            float a0 = fmaf(nki0, pos0, gv0);                                  \
            vs0  = fmaf(vs0, DAMP, a0);                                        \
            pos0 = fmaf(vs0, DAMP, pos0);                                      \
            float a1 = fmaf(nki1, pos1, gv1);                                  \
            vs1  = fmaf(vs1, DAMP, a1);                                        \
            pos1 = fmaf(vs1, DAMP, pos1);                                      \
            float t0 = tanh_fast(vs0);                                         \
            float t1 = tanh_fast(vs1);                                         \
            tile[(R) + i * 2 + s][lane] = fmaf(t0, micv0, t1 * micv1);         \
        }                                                                      \
    }

#define K3W(W, C00, C01, C10, C11, N00, N01, N10, N11)                         \
    {                                                                          \
        const int w_ = (W);                                                    \
        if (w_ + 1 < NWND) {                                                   \
            N00 = gw0[(size_t)(2 * (w_ + 1) + 0) * 64];                        \
            N01 = gw0[(size_t)(2 * (w_ + 1) + 1) * 64];                        \
            N10 = gw1[(size_t)(2 * (w_ + 1) + 0) * 64];                        \
            N11 = gw1[(size_t)(2 * (w_ + 1) + 1) * 64];                        \
        }                                                                      \
        K3_QQ(C00, C10, 0)                                                     \
        K3_QQ(C01, C11, 8)                                                     \
        __syncwarp();                                                          \
        const int row = lane & 15, cbb = (lane >> 4) * 16;                     \
        float s0 = 0.f, s1 = 0.f, s2 = 0.f, s3 = 0.f;                          \
        _Pragma("unroll")                                                      \
        for (int i = 0; i < 4; i++) {                                          \
            float4 v = *(const float4*)&tile[row][cbb + 4 * i];                \
            s0 += v.x; s1 += v.y; s2 += v.z; s3 += v.w;                        \
        }                                                                      \
        float sum = (s0 + s1) + (s2 + s3);                                     \
        sum += __shfl_down_sync(0xffffffffu, sum, 16);                         \
        if (lane < 16) __stcs(obase + w_ * 16 + lane, sum);                    \
        __syncwarp();                                                          \
    }

    for (int w = 0; w < NWND; w += 2) {
        K3W(w,     ca00, ca01, ca10, ca11, cb00, cb01, cb10, cb11)
        K3W(w + 1, cb00, cb01, cb10, cb11, ca00, ca01, ca10, ca11)
    }
#undef K3W
#undef K3_QQ
}

extern "C" void kernel_launch(void* const* d_in, const int* in_sizes, int n_in,
                              void* d_out, int out_size)
{
    const float* forces   = (const float*)d_in[0];
    const float* home     = (const float*)d_in[1];
    const float* mic      = (const float*)d_in[2];
    const float* masses   = (const float*)d_in[3];
    const float* tensions = (const float*)d_in[4];
    const float* gains    = (const float*)d_in[5];

    k0_homog<<<16, 256>>>(masses, tensions);
    for (int b = 0; b < 2; b++) {
        k1_passA  <<<512, 128>>>(forces, home, masses, tensions, gains, b);
        k2_combine<<<16,  256>>>();
        k3_passB  <<<512, 128>>>(mic, masses, tensions, (float*)d_out, b);
    }
}

// round 17
// speedup vs baseline: 1.1488x; 1.1488x over previous
#include <cuda_runtime.h>
#include <cuda_fp16.h>
#include <string.h>

// GooLayer: B=2, M=64, D=64, T=8192 — chunked linear-scan, 3 kernels
// (R14 structure) + sub-chunked pass B:
//  K1: pass A — stores g' = (f+ki*h)*(gain*DAMP) as fp16 (1-way noise-shaped
//      rounding); full-line coalesced f/h loads via smem staging; emits chunk
//      finals AND 256-step mid-states. g stores evict-normal (L2 handoff).
//  K2: combine — inline homogeneous M^256/M^512 + matvecs -> 32 sub-chunk ICs
//  K3: pass B — one warp per (bm, 256-step sub-chunk), all 64 d (2 chains/lane);
//      4096 warp-units -> ~28 warps/SM.

#define BBX 2
#define MMX 64
#define DDX 64
#define TTX 8192
#define DAMP 0.9998f
#define NCH 16
#define NSC 32                          // 256-step sub-chunks per bm
#define CL (TTX / NCH)                  // 512
#define NW8 (CL / 8)                    // 64 fp16-octet windows per chunk
#define K1NT (CL / 32)                  // 16 staging tiles per chunk
#define FQ (TTX / 4)                    // float4 per chain (2048)

// g scratch: [bm][chunk][w8][d] -> uint4 (8 fp16, t-ascending), coalesced in d
__device__ uint4 g_scr[(size_t)BBX * MMX * NCH * NW8 * DDX];
__device__ float g_fin[BBX * MMX * NCH * DDX * 2];
__device__ float g_mid[BBX * MMX * NCH * DDX * 2];
__device__ float g_ic [BBX * MMX * NSC * DDX * 2];

__device__ __forceinline__ float tanh_fast(float x) {
    float y; asm("tanh.approx.f32 %0, %1;" : "=f"(y) : "f"(x)); return y;
}
__device__ __forceinline__ __half2 u32_as_half2(unsigned u) {
    __half2 h; memcpy(&h, &u, 4); return h;
}
__device__ __forceinline__ unsigned half2_as_u32(__half2 h) {
    unsigned u; memcpy(&u, &h, 4); return u;
}

// ---------------- K1: pass A ----------------
// 128 threads = 4 warps; one warp per (bm, chunk, half) unit. 1024 blocks.
__global__ __launch_bounds__(128)
void k1_passA(const float* __restrict__ forces, const float* __restrict__ home,
              const float* __restrict__ masses, const float* __restrict__ tensions,
              const float* __restrict__ gains)
{
    __shared__ float gt[4][32][36];   // staged g' tiles: [warp][chain][t]
    __shared__ float kis[4][32];

    const int tid = threadIdx.x, wid = tid >> 5, lane = tid & 31;
    const int unit  = blockIdx.x * 4 + wid;        // 0..4095
    const int bm    = unit >> 5;                   // 0..127
    const int chunk = (unit >> 1) & 15;
    const int half  = unit & 1;
    const int m = bm & 63;
    const int d = half * 32 + lane;

    const float ki   = tensions[m * 64 + d] / masses[m];
    const float nki  = -ki;
    const float karg = gains[m] * DAMP;            // state scale (tanh arg)

    kis[wid][lane] = ki;
    __syncwarp();

    // per LDG.128: lanes cover 4 chains x 8 float4 (full 128B lines)
    const int lch4 = lane >> 3;                    // 0..3
    const int lt8  = lane & 7;                     // 0..7
    const size_t wb = ((size_t)(bm * 64 + half * 32)) * TTX + (size_t)chunk * CL;
    const float4* __restrict__ fbase = (const float4*)(forces + wb) + lt8;
    const float4* __restrict__ hbase = (const float4*)(home  + wb) + lt8;

    float kk0 = kis[wid][ 0 + lch4], kk1 = kis[wid][ 4 + lch4];
    float kk2 = kis[wid][ 8 + lch4], kk3 = kis[wid][12 + lch4];
    float kk4 = kis[wid][16 + lch4], kk5 = kis[wid][20 + lch4];
    float kk6 = kis[wid][24 + lch4], kk7 = kis[wid][28 + lch4];

    uint4* gw = g_scr + ((size_t)(bm * NCH + chunk) * NW8) * 64 + d;

    float pos = 0.f, vs = 0.f, e = 0.f;            // karg-scaled state

    float4 nf0, nf1, nf2, nf3, nf4, nf5, nf6, nf7;
    float4 nh0, nh1, nh2, nh3, nh4, nh5, nh6, nh7;

#define K1_LDALL(OFF)                                                          \
    nf0 = __ldcs(fbase + (size_t)(0 * 4 + lch4) * FQ + (OFF));                 \
    nf1 = __ldcs(fbase + (size_t)(1 * 4 + lch4) * FQ + (OFF));                 \
    nf2 = __ldcs(fbase + (size_t)(2 * 4 + lch4) * FQ + (OFF));                 \
    nf3 = __ldcs(fbase + (size_t)(3 * 4 + lch4) * FQ + (OFF));                 \
    nf4 = __ldcs(fbase + (size_t)(4 * 4 + lch4) * FQ + (OFF));                 \
    nf5 = __ldcs(fbase + (size_t)(5 * 4 + lch4) * FQ + (OFF));                 \
    nf6 = __ldcs(fbase + (size_t)(6 * 4 + lch4) * FQ + (OFF));                 \
    nf7 = __ldcs(fbase + (size_t)(7 * 4 + lch4) * FQ + (OFF));                 \
    nh0 = __ldcs(hbase + (size_t)(0 * 4 + lch4) * FQ + (OFF));                 \
    nh1 = __ldcs(hbase + (size_t)(1 * 4 + lch4) * FQ + (OFF));                 \
    nh2 = __ldcs(hbase + (size_t)(2 * 4 + lch4) * FQ + (OFF));                 \
    nh3 = __ldcs(hbase + (size_t)(3 * 4 + lch4) * FQ + (OFF));                 \
    nh4 = __ldcs(hbase + (size_t)(4 * 4 + lch4) * FQ + (OFF));                 \
    nh5 = __ldcs(hbase + (size_t)(5 * 4 + lch4) * FQ + (OFF));                 \
    nh6 = __ldcs(hbase + (size_t)(6 * 4 + lch4) * FQ + (OFF));                 \
    nh7 = __ldcs(hbase + (size_t)(7 * 4 + lch4) * FQ + (OFF));

#define K1_G4(NF, NH, KK)                                                      \
    make_float4(fmaf(KK, NH.x, NF.x) * karg, fmaf(KK, NH.y, NF.y) * karg,      \
                fmaf(KK, NH.z, NF.z) * karg, fmaf(KK, NH.w, NF.w) * karg)

    K1_LDALL(0)

    for (int tile = 0; tile < K1NT; tile++) {
        float4 ng0 = K1_G4(nf0, nh0, kk0), ng1 = K1_G4(nf1, nh1, kk1);
        float4 ng2 = K1_G4(nf2, nh2, kk2), ng3 = K1_G4(nf3, nh3, kk3);
        float4 ng4 = K1_G4(nf4, nh4, kk4), ng5 = K1_G4(nf5, nh5, kk5);
        float4 ng6 = K1_G4(nf6, nh6, kk6), ng7 = K1_G4(nf7, nh7, kk7);

        __syncwarp();
        *(float4*)&gt[wid][ 0 + lch4][lt8 * 4] = ng0;
        *(float4*)&gt[wid][ 4 + lch4][lt8 * 4] = ng1;
        *(float4*)&gt[wid][ 8 + lch4][lt8 * 4] = ng2;
        *(float4*)&gt[wid][12 + lch4][lt8 * 4] = ng3;
        *(float4*)&gt[wid][16 + lch4][lt8 * 4] = ng4;
        *(float4*)&gt[wid][20 + lch4][lt8 * 4] = ng5;
        *(float4*)&gt[wid][24 + lch4][lt8 * 4] = ng6;
        *(float4*)&gt[wid][28 + lch4][lt8 * 4] = ng7;
        __syncwarp();

        if (tile + 1 < K1NT) { K1_LDALL((tile + 1) * 8) }

        // 32 steps for chain = lane; quantize with 1-way error feedback
        unsigned uq0 = 0, uq1 = 0;
        #pragma unroll
        for (int j = 0; j < 8; j++) {
            float4 gv = *(const float4*)&gt[wid][lane][4 * j];
            __half q0, q1, q2, q3;
            float t, r, acc;

            t = gv.x + e; q0 = __float2half_rn(t); r = __half2float(q0); e = t - r;
            acc = fmaf(nki, pos, r); vs = fmaf(vs, DAMP, acc); pos = fmaf(vs, DAMP, pos);
            t = gv.y + e; q1 = __float2half_rn(t); r = __half2float(q1); e = t - r;
            acc = fmaf(nki, pos, r); vs = fmaf(vs, DAMP, acc); pos = fmaf(vs, DAMP, pos);
            t = gv.z + e; q2 = __float2half_rn(t); r = __half2float(q2); e = t - r;
            acc = fmaf(nki, pos, r); vs = fmaf(vs, DAMP, acc); pos = fmaf(vs, DAMP, pos);
            t = gv.w + e; q3 = __float2half_rn(t); r = __half2float(q3); e = t - r;
            acc = fmaf(nki, pos, r); vs = fmaf(vs, DAMP, acc); pos = fmaf(vs, DAMP, pos);

            unsigned ua = half2_as_u32(__halves2half2(q0, q1));  // q0 low
            unsigned ub = half2_as_u32(__halves2half2(q2, q3));
            if ((j & 1) == 0) { uq0 = ua; uq1 = ub; }
            else {
                uint4 pk; pk.x = uq0; pk.y = uq1; pk.z = ua; pk.w = ub;
                // evict-normal store: keep g resident in L2 for K3
                gw[(size_t)(tile * 4 + (j >> 1)) * 64] = pk;
            }
        }

        if (tile == K1NT / 2 - 1) {   // state after 256 steps
            float* mid = g_mid + ((size_t)(bm * NCH + chunk) * 64 + d) * 2;
            mid[0] = pos; mid[1] = vs;
        }
    }
#undef K1_LDALL
#undef K1_G4

    float* fin = g_fin + ((size_t)(bm * NCH + chunk) * 64 + d) * 2;
    fin[0] = pos; fin[1] = vs;
}

// ---------------- K2: combine — inline hom M^256/M^512, 32 sub-chunk ICs ----
__global__ __launch_bounds__(256)
void k2_combine(const float* __restrict__ masses, const float* __restrict__ tensions)
{
    int idx = blockIdx.x * 256 + threadIdx.x;      // bm*64+d, 0..8191
    int bm = idx >> 6, d = idx & 63, m = bm & 63;
    const float nki = -(tensions[m * 64 + d] / masses[m]);

    float p1 = 1.f, v1 = 0.f, p2 = 0.f, v2 = 1.f;
    #pragma unroll 8
    for (int t = 0; t < CL / 2; t++) {
        v1 = fmaf(v1, DAMP, nki * p1); p1 = fmaf(v1, DAMP, p1);
        v2 = fmaf(v2, DAMP, nki * p2); p2 = fmaf(v2, DAMP, p2);
    }
    const float q1 = p1, w1 = v1, q2 = p2, w2 = v2;   // M^256
    #pragma unroll 8
    for (int t = 0; t < CL / 2; t++) {
        v1 = fmaf(v1, DAMP, nki * p1); p1 = fmaf(v1, DAMP, p1);
        v2 = fmaf(v2, DAMP, nki * p2); p2 = fmaf(v2, DAMP, p2);
    }                                                  // M^512

    float pos = 0.f, vs = 0.f;
    #pragma unroll
    for (int c = 0; c < NCH; c++) {
        size_t om = ((size_t)(bm * NCH + c) * 64 + d) * 2;
        size_t oi = ((size_t)(bm * NSC + 2 * c) * 64 + d) * 2;
        g_ic[oi] = pos; g_ic[oi + 1] = vs;
        float mp = fmaf(q1, pos, fmaf(q2, vs, g_mid[om]));
        float mv = fmaf(w1, pos, fmaf(w2, vs, g_mid[om + 1]));
        size_t oj = ((size_t)(bm * NSC + 2 * c + 1) * 64 + d) * 2;
        g_ic[oj] = mp; g_ic[oj + 1] = mv;
        float np = fmaf(p1, pos, fmaf(p2, vs, g_fin[om]));
        float nv = fmaf(v1, pos, fmaf(v2, vs, g_fin[om + 1]));
        pos = np; vs = nv;
    }
}

// ---------------- K3: pass B — one warp per (bm, sub-chunk), 2 chains/lane --
// 1024 blocks x 128 threads = 4096 warp-units.
__global__ __launch_bounds__(128)
void k3_passB(const float* __restrict__ mic, const float* __restrict__ masses,
              const float* __restrict__ tensions, float* __restrict__ out)
{
    __shared__ float tile_s[4][16][36];

    const int tid = threadIdx.x, wid = tid >> 5, lane = tid & 31;
    const int unit = blockIdx.x * 4 + wid;         // 0..4095
    const int bm   = unit >> 5;                    // 0..127
    const int sc   = unit & 31;                    // sub-chunk (256 steps)
    const int chunk = sc >> 1;
    const int m = bm & 63;
    const int d0 = lane, d1 = lane + 32;

    const float inv_mass = 1.f / masses[m];
    const float nki0 = -(tensions[m * 64 + d0] * inv_mass);
    const float nki1 = -(tensions[m * 64 + d1] * inv_mass);
    const float micv0 = mic[bm * 64 + d0];
    const float micv1 = mic[bm * 64 + d1];

    const uint4* gw0 = g_scr + ((size_t)((bm * NCH + chunk) * NW8)
                                + (size_t)(sc & 1) * (NW8 / 2)) * 64 + d0;
    const uint4* gw1 = gw0 + 32;
    const size_t ib = ((size_t)(bm * NSC + sc) * 64) * 2;
    float pos0 = g_ic[ib + 2 * d0], vs0 = g_ic[ib + 2 * d0 + 1];
    float pos1 = g_ic[ib + 2 * d1], vs1 = g_ic[ib + 2 * d1 + 1];
    float* obase = out + (size_t)bm * TTX + (size_t)sc * (CL / 2);
    float (*tile)[36] = tile_s[wid];

    uint4 ca00, ca01, ca10, ca11, cb00, cb01, cb10, cb11;
    ca00 = gw0[0];  ca01 = gw0[64];   // default policy: L2 hits from K1
    ca10 = gw1[0];  ca11 = gw1[64];

    const int NWND = (CL / 2) / 16;                // 16 windows of 16 steps

#define K3_QQ(G0, G1, R)                                                       \
    _Pragma("unroll")                                                          \
    for (int i = 0; i < 4; i++) {                                              \
        float2 fa = __half22float2(u32_as_half2((&G0.x)[i]));                  \
        float2 fb = __half22float2(u32_as_half2((&G1.x)[i]));                  \
        _Pragma("unroll")                                                      \
        for (int s = 0; s < 2; s++) {                                          \
            float gv0 = s ? fa.y : fa.x;                                       \
            float gv1 = s ? fb.y : fb.x;                                       \
            float a0 = fmaf(nki0, pos0, gv0);                                  \
            vs0  = fmaf(vs0, DAMP, a0);                                        \
            pos0 = fmaf(vs0, DAMP, pos0);                                      \
            float a1 = fmaf(nki1, pos1, gv1);                                  \
            vs1  = fmaf(vs1, DAMP, a1);                                        \
            pos1 = fmaf(vs1, DAMP, pos1);                                      \
            float t0 = tanh_fast(vs0);                                         \
            float t1 = tanh_fast(vs1);                                         \
            tile[(R) + i * 2 + s][lane] = fmaf(t0, micv0, t1 * micv1);         \
        }                                                                      \
    }

#define K3W(W, C00, C01, C10, C11, N00, N01, N10, N11)                         \
    {                                                                          \
        const int w_ = (W);                                                    \
        if (w_ + 1 < NWND) {                                                   \
            N00 = gw0[(size_t)(2 * (w_ + 1) + 0) * 64];                        \
            N01 = gw0[(size_t)(2 * (w_ + 1) + 1) * 64];                        \
            N10 = gw1[(size_t)(2 * (w_ + 1) + 0) * 64];                        \
            N11 = gw1[(size_t)(2 * (w_ + 1) + 1) * 64];                        \
        }                                                                      \
        K3_QQ(C00, C10, 0)                                                     \
        K3_QQ(C01, C11, 8)                                                     \
        __syncwarp();                                                          \
        const int row = lane & 15, cbb = (lane >> 4) * 16;                     \
        float s0 = 0.f, s1 = 0.f, s2 = 0.f, s3 = 0.f;                          \
        _Pragma("unroll")                                                      \
        for (int i = 0; i < 4; i++) {                                          \
            float4 v = *(const float4*)&tile[row][cbb + 4 * i];                \
            s0 += v.x; s1 += v.y; s2 += v.z; s3 += v.w;                        \
        }                                                                      \
        float sum = (s0 + s1) + (s2 + s3);                                     \
        sum += __shfl_down_sync(0xffffffffu, sum, 16);                         \
        if (lane < 16) __stcs(obase + w_ * 16 + lane, sum);                    \
        __syncwarp();                                                          \
    }

    for (int w = 0; w < NWND; w += 2) {
        K3W(w,     ca00, ca01, ca10, ca11, cb00, cb01, cb10, cb11)
        K3W(w + 1, cb00, cb01, cb10, cb11, ca00, ca01, ca10, ca11)
    }
#undef K3W
#undef K3_QQ
}

extern "C" void kernel_launch(void* const* d_in, const int* in_sizes, int n_in,
                              void* d_out, int out_size)
{
    const float* forces   = (const float*)d_in[0];
    const float* home     = (const float*)d_in[1];
    const float* mic      = (const float*)d_in[2];
    const float* masses   = (const float*)d_in[3];
    const float* tensions = (const float*)d_in[4];
    const float* gains    = (const float*)d_in[5];

    k1_passA  <<<1024, 128>>>(forces, home, masses, tensions, gains);
    k2_combine<<<32,   256>>>(masses, tensions);
    k3_passB  <<<1024, 128>>>(mic, masses, tensions, (float*)d_out);
}